// round 12
// baseline (speedup 1.0000x reference)
#include <cuda_runtime.h>

// out[b,f] = x[b,f] * (log_sigma[f] < 1.0f ? e : 1.0f)
// BATCH=65536, N_FEATURES=4096 -> 2^26 float4. Pure HBM stream (2.15 GB).
//
// R12: 1024-thread blocks (CTA-coarsening paid 3x in a row) with 4
// front-batched float4 loads per thread. At 1024 thr/CTA occupancy is
// only ~2 CTAs/SM, so oe*MLP_p1 = 8 < 16 stays below the L1tex-queue
// contention knee that sank MLP4 at 256-thread blocks (R9).
// 16384 CTAs — half of R11's scheduling overhead.

#define N_FEATURES   4096
#define VEC4_PER_ROW (N_FEATURES / 4)            // 1024, power of two
#define TOTAL_VEC4   (65536LL * VEC4_PER_ROW)    // 2^26

#define THREADS  1024
#define BLOCKS   16384                            // 2^24 threads total
#define NSTRIDE  ((long long)THREADS * BLOCKS)    // 2^24, multiple of 1024

__global__ void __launch_bounds__(THREADS)
svdropout2d_kernel(const float4* __restrict__ x,
                   const float4* __restrict__ log_sigma,
                   float4* __restrict__ out)
{
    const float E = 2.71828182845904523536f;

    const long long i = (long long)blockIdx.x * THREADS + threadIdx.x;

    // Same column for all 4 elements (stride % 1024 == 0): one scale load.
    const int c = (int)(i & (VEC4_PER_ROW - 1));
    const float4 ls = __ldg(&log_sigma[c]);

    float4 s;
    s.x = (ls.x < 1.0f) ? E : 1.0f;
    s.y = (ls.y < 1.0f) ? E : 1.0f;
    s.z = (ls.z < 1.0f) ? E : 1.0f;
    s.w = (ls.w < 1.0f) ? E : 1.0f;

    // Front-batched independent loads (MLP_p1 = 4)
    float4 v0 = x[i + 0 * NSTRIDE];
    float4 v1 = x[i + 1 * NSTRIDE];
    float4 v2 = x[i + 2 * NSTRIDE];
    float4 v3 = x[i + 3 * NSTRIDE];

    v0.x *= s.x; v0.y *= s.y; v0.z *= s.z; v0.w *= s.w;
    v1.x *= s.x; v1.y *= s.y; v1.z *= s.z; v1.w *= s.w;
    v2.x *= s.x; v2.y *= s.y; v2.z *= s.z; v2.w *= s.w;
    v3.x *= s.x; v3.y *= s.y; v3.z *= s.z; v3.w *= s.w;

    out[i + 0 * NSTRIDE] = v0;
    out[i + 1 * NSTRIDE] = v1;
    out[i + 2 * NSTRIDE] = v2;
    out[i + 3 * NSTRIDE] = v3;
}

extern "C" void kernel_launch(void* const* d_in, const int* in_sizes, int n_in,
                              void* d_out, int out_size)
{
    const float4* x  = (const float4*)d_in[0];
    const float4* ls = (const float4*)d_in[1];
    float4* out      = (float4*)d_out;

    svdropout2d_kernel<<<BLOCKS, THREADS>>>(x, ls, out);
}

// round 13
// speedup vs baseline: 1.0214x; 1.0214x over previous
#include <cuda_runtime.h>

// out[b,f] = x[b,f] * (log_sigma[f] < 1.0f ? e : 1.0f)
// BATCH=65536, N_FEATURES=4096 -> 2^26 float4. Pure HBM stream (2.15 GB).
//
// R13: champion config (R11: 32768 x 1024, MLP_p1=2 front-batched float4
// loads — measured DRAM optimum 89.1% / 7.07 TB/s; MLP4 regressed at every
// block size, so MLP2 is intrinsic) + streaming cache hints on the
// zero-reuse x/out streams (evict-first; log_sigma stays cache-resident).

#define N_FEATURES   4096
#define VEC4_PER_ROW (N_FEATURES / 4)            // 1024, power of two
#define TOTAL_VEC4   (65536LL * VEC4_PER_ROW)    // 2^26

#define THREADS  1024
#define BLOCKS   32768                            // 2^25 threads total
#define NSTRIDE  ((long long)THREADS * BLOCKS)    // 2^25, multiple of 1024

__global__ void __launch_bounds__(THREADS)
svdropout2d_kernel(const float4* __restrict__ x,
                   const float4* __restrict__ log_sigma,
                   float4* __restrict__ out)
{
    const float E = 2.71828182845904523536f;

    const long long i = (long long)blockIdx.x * THREADS + threadIdx.x;

    // Same column for both elements (stride % 1024 == 0): one scale load.
    const int c = (int)(i & (VEC4_PER_ROW - 1));
    const float4 ls = __ldg(&log_sigma[c]);

    float4 s;
    s.x = (ls.x < 1.0f) ? E : 1.0f;
    s.y = (ls.y < 1.0f) ? E : 1.0f;
    s.z = (ls.z < 1.0f) ? E : 1.0f;
    s.w = (ls.w < 1.0f) ? E : 1.0f;

    // Front-batched independent loads (MLP_p1 = 2), streaming policy
    float4 v0 = __ldcs(&x[i]);
    float4 v1 = __ldcs(&x[i + NSTRIDE]);

    v0.x *= s.x; v0.y *= s.y; v0.z *= s.z; v0.w *= s.w;
    v1.x *= s.x; v1.y *= s.y; v1.z *= s.z; v1.w *= s.w;

    __stcs(&out[i],           v0);
    __stcs(&out[i + NSTRIDE], v1);
}

extern "C" void kernel_launch(void* const* d_in, const int* in_sizes, int n_in,
                              void* d_out, int out_size)
{
    const float4* x  = (const float4*)d_in[0];
    const float4* ls = (const float4*)d_in[1];
    float4* out      = (float4*)d_out;

    svdropout2d_kernel<<<BLOCKS, THREADS>>>(x, ls, out);
}